// round 2
// baseline (speedup 1.0000x reference)
#include <cuda_runtime.h>

#define HW     4096
#define WIDTH  64
#define CDIM   256
#define NH     8
#define HD     32
#define BATCH  2
#define SCALE  0.17677669529663687f

// Scratch (device globals; no allocation allowed)
__device__ float g_q[BATCH * NH * HW * HD];      // [b, head, p, d]
__device__ float g_k[BATCH * NH * HW * HD];      // [b, head, p, d]
__device__ float g_v[BATCH * NH * HW * HD];      // [b, head, p, d]
__device__ float g_attn[BATCH * HW * CDIM];      // [b, p, c]  c = head*32+d

// ---------------------------------------------------------------------------
// Kernel 1: QKV projection. M=768 (3 types x 8 heads x 32 d), K=256, N=4096,
// batch 2. Tile 128x64, 256 threads, 8x4 microtile. A stored k-major in smem
// so the inner loop is 2 LDS.128 (A) + 1 LDS.128 (B) per 32 FFMA.
// ---------------------------------------------------------------------------
__global__ __launch_bounds__(256) void qkv_gemm_kernel(
    const float* __restrict__ x,
    const float* __restrict__ w0, const float* __restrict__ bb0,
    const float* __restrict__ w1, const float* __restrict__ bb1,
    const float* __restrict__ w2, const float* __restrict__ bb2)
{
    __shared__ float As[16][132];          // [k][m]
    __shared__ float Bs[16][68];           // [k][n]
    __shared__ const float* Arow[128];
    __shared__ float biasS[128];

    const int tid  = threadIdx.x;
    const int row0 = blockIdx.y * 128;
    const int col0 = blockIdx.x * 64;
    const int b    = blockIdx.z;

    if (tid < 128) {
        int M = row0 + tid;
        int t = M >> 8;            // 0=q, 1=k, 2=v
        int rem = M & 255;         // head*32 + d
        int head = rem >> 5;
        const float* w; const float* bb;
        if (head < 4)      { w = w0; bb = bb0; }
        else if (head < 7) { w = w1; bb = bb1; }
        else               { w = w2; bb = bb2; }
        Arow[tid]  = w + (size_t)(t * 256 + rem) * 256;
        biasS[tid] = bb[t * 256 + rem];
    }
    __syncthreads();

    const int tx = tid & 15, ty = tid >> 4;          // n:16x4, m:16x8
    const int am = tid >> 1, akq = (tid & 1) * 8;    // A-load mapping
    const int bk = tid >> 4, bn = (tid & 15) * 4;    // B-load mapping
    float acc[8][4] = {};
    const float* xb = x + (size_t)b * CDIM * HW;

    for (int k0 = 0; k0 < 256; k0 += 16) {
        {   // A tile: 128 rows x 16 k, transposed into As[k][m]
            const float* src = Arow[am] + k0 + akq;
            float4 a0 = *(const float4*)(src);
            float4 a1 = *(const float4*)(src + 4);
            As[akq + 0][am] = a0.x; As[akq + 1][am] = a0.y;
            As[akq + 2][am] = a0.z; As[akq + 3][am] = a0.w;
            As[akq + 4][am] = a1.x; As[akq + 5][am] = a1.y;
            As[akq + 6][am] = a1.z; As[akq + 7][am] = a1.w;
        }
        {   // B tile: 16 k x 64 n, coalesced along n
            float4 bv = *(const float4*)(xb + (size_t)(k0 + bk) * HW + col0 + bn);
            *(float4*)&Bs[bk][bn] = bv;
        }
        __syncthreads();
        #pragma unroll
        for (int kk = 0; kk < 16; kk++) {
            float4 a0 = *(float4*)&As[kk][ty * 8];
            float4 a1 = *(float4*)&As[kk][ty * 8 + 4];
            float4 bv = *(float4*)&Bs[kk][tx * 4];
            float a[8] = {a0.x, a0.y, a0.z, a0.w, a1.x, a1.y, a1.z, a1.w};
            float bl[4] = {bv.x, bv.y, bv.z, bv.w};
            #pragma unroll
            for (int i = 0; i < 8; i++)
                #pragma unroll
                for (int j = 0; j < 4; j++)
                    acc[i][j] += a[i] * bl[j];
        }
        __syncthreads();
    }

    #pragma unroll
    for (int i = 0; i < 8; i++) {
        int M = row0 + ty * 8 + i;
        int t = M >> 8, rem = M & 255, head = rem >> 5, d = rem & 31;
        float* dst = (t == 0) ? g_q : (t == 1) ? g_k : g_v;
        float bias = biasS[ty * 8 + i];
        int base = ((b * NH + head) * HW) * HD + d;
        #pragma unroll
        for (int j = 0; j < 4; j++) {
            int p = col0 + tx * 4 + j;
            dst[base + p * HD] = acc[i][j] + bias;
        }
    }
}

// ---------------------------------------------------------------------------
// Kernel 2: neighborhood attention. One warp per (b, head, pixel).
// Logits phase: lane = neighbor (full 32-d dot per lane, no shuffles).
// PV phase: lane = d (one shfl broadcast per neighbor).
// OOB neighbors keep logit=0 inside the softmax (F.unfold zero padding).
// ---------------------------------------------------------------------------
template <int KSZ, int DIL>
__device__ __forceinline__ void attn_body(int lane, int b, int head, int p)
{
    constexpr int L = KSZ * KSZ;
    constexpr int NL = (L + 31) / 32;
    constexpr int HALF = KSZ / 2;

    const int y = p >> 6, x = p & 63;
    const int hb = ((b * NH + head) * HW) * HD;
    const float* __restrict__ kb = g_k + hb;
    const float* __restrict__ vb = g_v + hb;

    // q (scaled) in registers, replicated per lane
    float4 qv[8];
    {
        const float4* qr = (const float4*)(g_q + hb + p * HD);
        #pragma unroll
        for (int j = 0; j < 8; j++) {
            float4 t = qr[j];
            qv[j] = make_float4(t.x * SCALE, t.y * SCALE, t.z * SCALE, t.w * SCALE);
        }
    }

    // Logits: lane handles neighbor idx = pass*32 + lane
    float lgs[NL];
    #pragma unroll
    for (int pass = 0; pass < NL; pass++) {
        const int idx = pass * 32 + lane;
        float s = 0.f;
        if (idx < L) {
            const int ky = idx / KSZ, kx = idx % KSZ;
            const int ny = y + (ky - HALF) * DIL;
            const int nx = x + (kx - HALF) * DIL;
            if ((unsigned)ny < 64u && (unsigned)nx < 64u) {
                const float4* kr = (const float4*)(kb + (ny * 64 + nx) * HD);
                #pragma unroll
                for (int j = 0; j < 8; j++) {
                    float4 kv = kr[j];
                    s += qv[j].x * kv.x + qv[j].y * kv.y
                       + qv[j].z * kv.z + qv[j].w * kv.w;
                }
            }
        }
        lgs[pass] = s;
    }

    // Softmax across the L logits (lane-strided storage)
    float mx = -1e30f;
    #pragma unroll
    for (int j = 0; j < NL; j++)
        if (j * 32 + lane < L) mx = fmaxf(mx, lgs[j]);
    #pragma unroll
    for (int o = 16; o > 0; o >>= 1)
        mx = fmaxf(mx, __shfl_xor_sync(0xffffffffu, mx, o));

    float e[NL];
    float sum = 0.f;
    #pragma unroll
    for (int j = 0; j < NL; j++) {
        e[j] = (j * 32 + lane < L) ? __expf(lgs[j] - mx) : 0.f;
        sum += e[j];
    }
    #pragma unroll
    for (int o = 16; o > 0; o >>= 1)
        sum += __shfl_xor_sync(0xffffffffu, sum, o);
    const float inv = 1.f / sum;

    // PV: lane = d
    float acc = 0.f;
    #pragma unroll
    for (int ky = 0; ky < KSZ; ky++) {
        const int ny = y + (ky - HALF) * DIL;
        #pragma unroll
        for (int kx = 0; kx < KSZ; kx++) {
            const int l = ky * KSZ + kx;
            const int nx = x + (kx - HALF) * DIL;
            if ((unsigned)ny < 64u && (unsigned)nx < 64u) {
                float pl = __shfl_sync(0xffffffffu, e[l >> 5], l & 31) * inv;
                acc += pl * vb[(ny * 64 + nx) * HD + lane];
            }
        }
    }

    g_attn[(b * HW + p) * CDIM + head * HD + lane] = acc;
}

__global__ __launch_bounds__(256) void attn_kernel()
{
    const int lane = threadIdx.x & 31;
    const int wid  = threadIdx.x >> 5;
    const int W    = blockIdx.x * 8 + wid;
    const int p    = W & (HW - 1);
    const int head = (W >> 12) & 7;
    const int b    = W >> 15;

    if (head < 4)      attn_body<5, 1>(lane, b, head, p);
    else if (head < 7) attn_body<7, 2>(lane, b, head, p);
    else               attn_body<9, 3>(lane, b, head, p);
}

// ---------------------------------------------------------------------------
// Kernel 3: output projection. out[b,o,p] = sum_c attn[b,p,c]*pw[o,c] + pb[o].
// M=256, K=256, N=4096, batch 2. Tile 128x64, 8x4 microtile.
// ---------------------------------------------------------------------------
__global__ __launch_bounds__(256) void proj_gemm_kernel(
    const float* __restrict__ pw, const float* __restrict__ pb,
    float* __restrict__ out)
{
    __shared__ float As[16][132];   // [k][m]
    __shared__ float Bs[16][68];    // [k][n]

    const int tid  = threadIdx.x;
    const int row0 = blockIdx.y * 128;
    const int col0 = blockIdx.x * 64;
    const int b    = blockIdx.z;

    const int tx = tid & 15, ty = tid >> 4;
    const int am = tid >> 1, akq = (tid & 1) * 8;
    const int bp = tid >> 2, bcq = (tid & 3) * 4;
    float acc[8][4] = {};
    const float* attb = g_attn + (size_t)b * HW * CDIM;

    for (int k0 = 0; k0 < 256; k0 += 16) {
        {   // A tile: proj_w rows, transposed into As[k][m]
            const float* src = pw + (size_t)(row0 + am) * 256 + k0 + akq;
            float4 a0 = *(const float4*)(src);
            float4 a1 = *(const float4*)(src + 4);
            As[akq + 0][am] = a0.x; As[akq + 1][am] = a0.y;
            As[akq + 2][am] = a0.z; As[akq + 3][am] = a0.w;
            As[akq + 4][am] = a1.x; As[akq + 5][am] = a1.y;
            As[akq + 6][am] = a1.z; As[akq + 7][am] = a1.w;
        }
        {   // B tile: attn is [p, c] -> transpose into Bs[c][p]
            float4 bv = *(const float4*)(attb + (size_t)(col0 + bp) * CDIM + k0 + bcq);
            Bs[bcq + 0][bp] = bv.x;
            Bs[bcq + 1][bp] = bv.y;
            Bs[bcq + 2][bp] = bv.z;
            Bs[bcq + 3][bp] = bv.w;
        }
        __syncthreads();
        #pragma unroll
        for (int kk = 0; kk < 16; kk++) {
            float4 a0 = *(float4*)&As[kk][ty * 8];
            float4 a1 = *(float4*)&As[kk][ty * 8 + 4];
            float4 bv = *(float4*)&Bs[kk][tx * 4];
            float a[8] = {a0.x, a0.y, a0.z, a0.w, a1.x, a1.y, a1.z, a1.w};
            float bl[4] = {bv.x, bv.y, bv.z, bv.w};
            #pragma unroll
            for (int i = 0; i < 8; i++)
                #pragma unroll
                for (int j = 0; j < 4; j++)
                    acc[i][j] += a[i] * bl[j];
        }
        __syncthreads();
    }

    #pragma unroll
    for (int i = 0; i < 8; i++) {
        int o = row0 + ty * 8 + i;
        float bias = pb[o];
        float4 ov = make_float4(acc[i][0] + bias, acc[i][1] + bias,
                                acc[i][2] + bias, acc[i][3] + bias);
        *(float4*)(out + ((size_t)b * CDIM + o) * HW + col0 + tx * 4) = ov;
    }
}

// ---------------------------------------------------------------------------
extern "C" void kernel_launch(void* const* d_in, const int* in_sizes, int n_in,
                              void* d_out, int out_size)
{
    const float* x   = (const float*)d_in[0];
    const float* w0  = (const float*)d_in[1];
    const float* bb0 = (const float*)d_in[2];
    const float* w1  = (const float*)d_in[3];
    const float* bb1 = (const float*)d_in[4];
    const float* w2  = (const float*)d_in[5];
    const float* bb2 = (const float*)d_in[6];
    const float* pw  = (const float*)d_in[7];
    const float* pb  = (const float*)d_in[8];
    float* out = (float*)d_out;

    qkv_gemm_kernel<<<dim3(HW / 64, 768 / 128, BATCH), 256>>>(
        x, w0, bb0, w1, bb1, w2, bb2);

    attn_kernel<<<(BATCH * NH * HW) / 8, 256>>>();

    proj_gemm_kernel<<<dim3(HW / 64, CDIM / 128, BATCH), 256>>>(pw, pb, out);
}

// round 3
// speedup vs baseline: 1.0952x; 1.0952x over previous
#include <cuda_runtime.h>

#define HW     4096
#define WIDTH  64
#define CDIM   256
#define NH     8
#define HD     32
#define BATCH  2
#define SCALE  0.17677669529663687f

// Scratch (device globals; no allocation allowed)
__device__ float g_q[BATCH * NH * HW * HD];      // [b, head, p, d]
__device__ float g_k[BATCH * NH * HW * HD];      // [b, head, p, d]
__device__ float g_v[BATCH * NH * HW * HD];      // [b, head, p, d]
__device__ float g_attn[BATCH * HW * CDIM];      // [b, p, c]  c = head*32+d

// ---------------------------------------------------------------------------
// Kernel 1: QKV projection (R1 version, 64x64 tile, 4x4 microtile).
// ---------------------------------------------------------------------------
__global__ __launch_bounds__(256) void qkv_gemm_kernel(
    const float* __restrict__ x,
    const float* __restrict__ w0, const float* __restrict__ bb0,
    const float* __restrict__ w1, const float* __restrict__ bb1,
    const float* __restrict__ w2, const float* __restrict__ bb2)
{
    __shared__ float As[64][16];
    __shared__ float Bs[16][68];
    __shared__ const float* Arow[64];
    __shared__ float biasS[64];

    const int tid  = threadIdx.x;
    const int row0 = blockIdx.y * 64;
    const int col0 = blockIdx.x * 64;
    const int b    = blockIdx.z;

    if (tid < 64) {
        int M = row0 + tid;
        int t = M >> 8;            // 0=q, 1=k, 2=v
        int rem = M & 255;         // head*32 + d
        int head = rem >> 5;
        const float* w; const float* bb;
        if (head < 4)      { w = w0; bb = bb0; }
        else if (head < 7) { w = w1; bb = bb1; }
        else               { w = w2; bb = bb2; }
        Arow[tid]  = w + (size_t)(t * 256 + rem) * 256;
        biasS[tid] = bb[t * 256 + rem];
    }
    __syncthreads();

    const int tx = tid & 15, ty = tid >> 4;
    float acc[4][4] = {};
    const float* xb = x + (size_t)b * CDIM * HW;

    for (int k0 = 0; k0 < 256; k0 += 16) {
        {   // load A tile (64x16): one float4 per thread
            int m = tid >> 2, k = (tid & 3) * 4;
            float4 av = *(const float4*)(Arow[m] + k0 + k);
            *(float4*)&As[m][k] = av;
        }
        {   // load B tile (16x64): one float4 per thread, coalesced along n
            int k = tid >> 4, n = (tid & 15) * 4;
            float4 bv = *(const float4*)(xb + (size_t)(k0 + k) * HW + col0 + n);
            *(float4*)&Bs[k][n] = bv;
        }
        __syncthreads();
        #pragma unroll
        for (int kk = 0; kk < 16; kk++) {
            float a[4];
            #pragma unroll
            for (int i = 0; i < 4; i++) a[i] = As[ty * 4 + i][kk];
            float4 bv = *(float4*)&Bs[kk][tx * 4];
            float bl[4] = {bv.x, bv.y, bv.z, bv.w};
            #pragma unroll
            for (int i = 0; i < 4; i++)
                #pragma unroll
                for (int j = 0; j < 4; j++)
                    acc[i][j] += a[i] * bl[j];
        }
        __syncthreads();
    }

    #pragma unroll
    for (int i = 0; i < 4; i++) {
        int M = row0 + ty * 4 + i;
        int t = M >> 8, rem = M & 255, head = rem >> 5, d = rem & 31;
        float* dst = (t == 0) ? g_q : (t == 1) ? g_k : g_v;
        float bias = biasS[ty * 4 + i];
        int base = ((b * NH + head) * HW) * HD + d;
        #pragma unroll
        for (int j = 0; j < 4; j++) {
            int p = col0 + tx * 4 + j;
            dst[base + p * HD] = acc[i][j] + bias;
        }
    }
}

// ---------------------------------------------------------------------------
// Kernel 2: neighborhood attention. One warp per (b, head, pixel); lane = d.
// Logits: per batch of 32 neighbors, each lane computes its per-d product for
// all 32 neighbors, then ONE 31-shuffle butterfly transpose-reduction leaves
// lane l holding the full logit of neighbor (batch*32 + l). ~1 SHFL/neighbor
// instead of 5, with K loads still fully coalesced (one 128B line per warp).
// OOB neighbors keep logit = 0 inside the softmax (F.unfold zero padding).
// ---------------------------------------------------------------------------
template <int KSZ, int DIL>
__device__ __forceinline__ void attn_body(int lane, int b, int head, int p)
{
    constexpr int L = KSZ * KSZ;
    constexpr int NL = (L + 31) / 32;
    constexpr int HALF = KSZ / 2;

    const int y = p >> 6, x = p & 63;
    const int hb = ((b * NH + head) * HW) * HD;
    const float* __restrict__ kb = g_k + hb;
    const float* __restrict__ vb = g_v + hb;

    const float q = g_q[hb + p * HD + lane] * SCALE;

    float lgs[NL];
    #pragma unroll
    for (int batch = 0; batch < NL; batch++) {
        float v[32];
        #pragma unroll
        for (int j = 0; j < 32; j++) {
            const int idx = batch * 32 + j;
            float kval = 0.f;
            if (idx < L) {
                const int ky = idx / KSZ, kx = idx % KSZ;
                const int ny = y + (ky - HALF) * DIL;
                const int nx = x + (kx - HALF) * DIL;
                if ((unsigned)ny < 64u && (unsigned)nx < 64u)
                    kval = kb[(ny * 64 + nx) * HD + lane];
            }
            v[j] = q * kval;
        }
        // Butterfly transpose-reduction: after all stages, v[0] at lane l is
        // the total (over d) for neighbor slot batch*32 + l.
        #pragma unroll
        for (int m = 16; m >= 1; m >>= 1) {
            const bool up = (lane & m) != 0;
            #pragma unroll
            for (int j = 0; j < m; j++) {
                float send = up ? v[j] : v[j + m];
                float recv = __shfl_xor_sync(0xffffffffu, send, m);
                v[j] = (up ? v[j + m] : v[j]) + recv;
            }
        }
        lgs[batch] = v[0];
    }

    // Softmax across L logits (lane-strided storage: slot j*32+lane)
    float mx = -1e30f;
    #pragma unroll
    for (int j = 0; j < NL; j++)
        if (j * 32 + lane < L) mx = fmaxf(mx, lgs[j]);
    #pragma unroll
    for (int o = 16; o > 0; o >>= 1)
        mx = fmaxf(mx, __shfl_xor_sync(0xffffffffu, mx, o));

    float e[NL];
    float sum = 0.f;
    #pragma unroll
    for (int j = 0; j < NL; j++) {
        e[j] = (j * 32 + lane < L) ? __expf(lgs[j] - mx) : 0.f;
        sum += e[j];
    }
    #pragma unroll
    for (int o = 16; o > 0; o >>= 1)
        sum += __shfl_xor_sync(0xffffffffu, sum, o);
    const float inv = 1.f / sum;

    // PV: lane = d, one broadcast shuffle per neighbor
    float acc = 0.f;
    #pragma unroll
    for (int ky = 0; ky < KSZ; ky++) {
        const int ny = y + (ky - HALF) * DIL;
        #pragma unroll
        for (int kx = 0; kx < KSZ; kx++) {
            const int l = ky * KSZ + kx;
            const int nx = x + (kx - HALF) * DIL;
            if ((unsigned)ny < 64u && (unsigned)nx < 64u) {
                float pl = __shfl_sync(0xffffffffu, e[l >> 5], l & 31) * inv;
                acc += pl * vb[(ny * 64 + nx) * HD + lane];
            }
        }
    }

    g_attn[(b * HW + p) * CDIM + head * HD + lane] = acc;
}

__global__ __launch_bounds__(256) void attn_kernel()
{
    const int lane = threadIdx.x & 31;
    const int wid  = threadIdx.x >> 5;
    const int W    = blockIdx.x * 8 + wid;
    const int p    = W & (HW - 1);
    const int head = (W >> 12) & 7;
    const int b    = W >> 15;

    if (head < 4)      attn_body<5, 1>(lane, b, head, p);
    else if (head < 7) attn_body<7, 2>(lane, b, head, p);
    else               attn_body<9, 3>(lane, b, head, p);
}

// ---------------------------------------------------------------------------
// Kernel 3: output projection (R1 version, 64x64 tile, 4x4 microtile).
// ---------------------------------------------------------------------------
__global__ __launch_bounds__(256) void proj_gemm_kernel(
    const float* __restrict__ pw, const float* __restrict__ pb,
    float* __restrict__ out)
{
    __shared__ float As[64][16];
    __shared__ float Bs[16][68];

    const int tid  = threadIdx.x;
    const int row0 = blockIdx.y * 64;
    const int col0 = blockIdx.x * 64;
    const int b    = blockIdx.z;

    const int tx = tid & 15, ty = tid >> 4;
    float acc[4][4] = {};
    const float* attb = g_attn + (size_t)b * HW * CDIM;

    for (int k0 = 0; k0 < 256; k0 += 16) {
        {   // A tile: proj_w rows
            int m = tid >> 2, k = (tid & 3) * 4;
            *(float4*)&As[m][k] =
                *(const float4*)(pw + (size_t)(row0 + m) * 256 + k0 + k);
        }
        {   // B tile: attn is [p, c] -> transpose into Bs[k][n]
            int n = tid >> 2, k = (tid & 3) * 4;
            float4 bv = *(const float4*)(attb + (size_t)(col0 + n) * CDIM + k0 + k);
            Bs[k][n]     = bv.x;
            Bs[k + 1][n] = bv.y;
            Bs[k + 2][n] = bv.z;
            Bs[k + 3][n] = bv.w;
        }
        __syncthreads();
        #pragma unroll
        for (int kk = 0; kk < 16; kk++) {
            float a[4];
            #pragma unroll
            for (int i = 0; i < 4; i++) a[i] = As[ty * 4 + i][kk];
            float4 bv = *(float4*)&Bs[kk][tx * 4];
            float bl[4] = {bv.x, bv.y, bv.z, bv.w};
            #pragma unroll
            for (int i = 0; i < 4; i++)
                #pragma unroll
                for (int j = 0; j < 4; j++)
                    acc[i][j] += a[i] * bl[j];
        }
        __syncthreads();
    }

    #pragma unroll
    for (int i = 0; i < 4; i++) {
        int o = row0 + ty * 4 + i;
        float bias = pb[o];
        float4 ov = make_float4(acc[i][0] + bias, acc[i][1] + bias,
                                acc[i][2] + bias, acc[i][3] + bias);
        *(float4*)(out + ((size_t)b * CDIM + o) * HW + col0 + tx * 4) = ov;
    }
}

// ---------------------------------------------------------------------------
extern "C" void kernel_launch(void* const* d_in, const int* in_sizes, int n_in,
                              void* d_out, int out_size)
{
    const float* x   = (const float*)d_in[0];
    const float* w0  = (const float*)d_in[1];
    const float* bb0 = (const float*)d_in[2];
    const float* w1  = (const float*)d_in[3];
    const float* bb1 = (const float*)d_in[4];
    const float* w2  = (const float*)d_in[5];
    const float* bb2 = (const float*)d_in[6];
    const float* pw  = (const float*)d_in[7];
    const float* pb  = (const float*)d_in[8];
    float* out = (float*)d_out;

    qkv_gemm_kernel<<<dim3(HW / 64, 768 / 64, BATCH), 256>>>(
        x, w0, bb0, w1, bb1, w2, bb2);

    attn_kernel<<<(BATCH * NH * HW) / 8, 256>>>();

    proj_gemm_kernel<<<dim3(HW / 64, CDIM / 64, BATCH), 256>>>(pw, pb, out);
}